// round 16
// baseline (speedup 1.0000x reference)
#include <cuda_runtime.h>
#include <math.h>

// ---------------- problem constants (fixed shapes in the dataset) -----------
#define Bc   64
#define Sc   128
#define Dc   2048
#define Pc   118
#define Cc   2
#define Vc   512

#define D4c  (Dc/4)            // 512 float4 per zs/rzs row
#define PCc  (Pc*Cc)           // 236
#define PC4c (PCc/4)           // 59
#define V4c  (Vc/4)            // 128

#define NROW (Bc*Sc)           // 8192 rows
#define NRP  (NROW/2)          // 4096 row-pairs (2 rows = 1024 float4 = 1 block-iter)
#define R1c  (NROW*D4c)        // 4,194,304  recon vec4s
#define R2c  (NROW*PC4c)       //   483,328  pts vec4s
#define R3c  (NROW*V4c)        // 1,048,576  kld vec4s
#define R4c  (Bc*PC4c)         //     3,776  best vec4s

#define NBLK 152               // 1 CTA/SM x 152 SMs — occ 1
#define NTHR 1024
#define STRIDEc (NBLK*NTHR)    // 155,648

#define EPSf  1e-20f
#define LOGGf (-6.23832462503951f)   // log(1/512)

// global accumulators: recon, disk, lm, kld, best, bestlm  (+pad)
__device__ float        g_acc[8];
__device__ unsigned int g_cnt;

__device__ __forceinline__ bool is_mark(int p) {
    return (p == 0) | (p == 29) | (p == 88) | (p == 117);
}

__global__ __launch_bounds__(NTHR) void loss_fused(
    const float4* __restrict__ zs,
    const float4* __restrict__ rzs,
    const float4* __restrict__ pts,
    const float4* __restrict__ pts_gt,
    const float4* __restrict__ qy,
    const float4* __restrict__ best,
    const float4* __restrict__ best_gt,
    const int*    __restrict__ map32,   // mapping viewed as int32 words
    float*        __restrict__ out)
{
    const int t    = threadIdx.x;
    const int gtid = blockIdx.x * NTHR + t;

    // ---- detect mapping width once: int64 (JAX default) vs int32 ----------
    __shared__ int s_sh;
    if (t == 0) {
        int nz = 0;
        #pragma unroll
        for (int i = 0; i < 64; i++) nz |= map32[2 * i + 1];
        s_sh = (nz == 0) ? 1 : 0;   // shift: row<<1 for int64, row<<0 for int32
    }
    __syncthreads();
    const int sh = s_sh;

    float recon = 0.f, disk = 0.f, lm = 0.f, kld = 0.f, bsum = 0.f, blm = 0.f;

    // Cache policy (champion): evict-first (__ldcs) on all sequential
    // single-use streams (zs, pts_gt, qy, best, best_gt); DEFAULT policy on
    // the gathered tensors (rzs, pts).

    // ===== Region 1: recon — 4 row-pairs per iteration (8 big loads) =======
    // 1024 threads: thread t owns float4 (t&511) of row (2*rp + (t>>9)).
    {
        float recon0 = 0.f, recon1 = 0.f, recon2 = 0.f, recon3 = 0.f;
        const int rsub = t >> 9;          // 0 or 1: which row of the pair
        const int col  = t & 511;
        int rp = blockIdx.x;
        for (; rp + 3 * NBLK < NRP; rp += 4 * NBLK) {
            int row0 = (rp << 1) + rsub;
            int row1 = ((rp + NBLK) << 1) + rsub;
            int row2 = ((rp + 2 * NBLK) << 1) + rsub;
            int row3 = ((rp + 3 * NBLK) << 1) + rsub;
            int m0 = __ldg(&map32[row0 << sh]);
            int m1 = __ldg(&map32[row1 << sh]);
            int m2 = __ldg(&map32[row2 << sh]);
            int m3 = __ldg(&map32[row3 << sh]);
            int rb0 = ((((row0 >> 7) << 7) + m0) << 9) + col;
            int rb1 = ((((row1 >> 7) << 7) + m1) << 9) + col;
            int rb2 = ((((row2 >> 7) << 7) + m2) << 9) + col;
            int rb3 = ((((row3 >> 7) << 7) + m3) << 9) + col;
            float4 z0 = __ldcs(&zs[(row0 << 9) + col]);
            float4 z1 = __ldcs(&zs[(row1 << 9) + col]);
            float4 z2 = __ldcs(&zs[(row2 << 9) + col]);
            float4 z3 = __ldcs(&zs[(row3 << 9) + col]);
            float4 r0 = rzs[rb0];
            float4 r1 = rzs[rb1];
            float4 r2 = rzs[rb2];
            float4 r3 = rzs[rb3];
            float d;
            d = z0.x - r0.x; recon0 += d * d;
            d = z0.y - r0.y; recon0 += d * d;
            d = z0.z - r0.z; recon0 += d * d;
            d = z0.w - r0.w; recon0 += d * d;
            d = z1.x - r1.x; recon1 += d * d;
            d = z1.y - r1.y; recon1 += d * d;
            d = z1.z - r1.z; recon1 += d * d;
            d = z1.w - r1.w; recon1 += d * d;
            d = z2.x - r2.x; recon2 += d * d;
            d = z2.y - r2.y; recon2 += d * d;
            d = z2.z - r2.z; recon2 += d * d;
            d = z2.w - r2.w; recon2 += d * d;
            d = z3.x - r3.x; recon3 += d * d;
            d = z3.y - r3.y; recon3 += d * d;
            d = z3.z - r3.z; recon3 += d * d;
            d = z3.w - r3.w; recon3 += d * d;
        }
        for (; rp < NRP; rp += NBLK) {
            int row = (rp << 1) + rsub;
            int m   = __ldg(&map32[row << sh]);
            int rb  = ((((row >> 7) << 7) + m) << 9) + col;
            float4 z = __ldcs(&zs[(row << 9) + col]);
            float4 r = rzs[rb];
            float dx = z.x - r.x, dy = z.y - r.y, dz = z.z - r.z, dw = z.w - r.w;
            recon0 += dx * dx + dy * dy + dz * dz + dw * dw;
        }
        recon = (recon0 + recon1) + (recon2 + recon3);
    }

    // ===== Region 2: pts gather + landmark =================================
    {
        for (int e = gtid; e < R2c; e += STRIDEc) {
            int row = e / PC4c;
            int j4  = e - row * PC4c;
            int m   = __ldg(&map32[row << sh]);
            int pb  = (((row >> 7) << 7) + m) * PC4c + j4;
            float4 g = __ldcs(&pts_gt[e]);
            float4 x = pts[pb];
            int p0 = j4 * 2, p1 = p0 + 1;   // C=2: (x,y)->point p0, (z,w)->p1
            float dx = x.x - g.x, dy = x.y - g.y, dz = x.z - g.z, dw = x.w - g.w;
            float s01 = dx * dx + dy * dy;
            float s23 = dz * dz + dw * dw;
            disk += s01 + s23;
            if (is_mark(p0)) lm += s01;
            if (is_mark(p1)) lm += s23;
        }
    }

    // ===== Region 3: KL vs uniform — evict-first stream, unrolled x4 =======
    {
        float k0 = 0.f, k1 = 0.f, k2 = 0.f, k3 = 0.f;
        int e = gtid;
        for (; e + 3 * STRIDEc < R3c; e += 4 * STRIDEc) {
            float4 q0 = __ldcs(&qy[e]);
            float4 q1 = __ldcs(&qy[e + STRIDEc]);
            float4 q2 = __ldcs(&qy[e + 2 * STRIDEc]);
            float4 q3 = __ldcs(&qy[e + 3 * STRIDEc]);
            k0 += q0.x * (__logf(q0.x + EPSf) - LOGGf)
                + q0.y * (__logf(q0.y + EPSf) - LOGGf)
                + q0.z * (__logf(q0.z + EPSf) - LOGGf)
                + q0.w * (__logf(q0.w + EPSf) - LOGGf);
            k1 += q1.x * (__logf(q1.x + EPSf) - LOGGf)
                + q1.y * (__logf(q1.y + EPSf) - LOGGf)
                + q1.z * (__logf(q1.z + EPSf) - LOGGf)
                + q1.w * (__logf(q1.w + EPSf) - LOGGf);
            k2 += q2.x * (__logf(q2.x + EPSf) - LOGGf)
                + q2.y * (__logf(q2.y + EPSf) - LOGGf)
                + q2.z * (__logf(q2.z + EPSf) - LOGGf)
                + q2.w * (__logf(q2.w + EPSf) - LOGGf);
            k3 += q3.x * (__logf(q3.x + EPSf) - LOGGf)
                + q3.y * (__logf(q3.y + EPSf) - LOGGf)
                + q3.z * (__logf(q3.z + EPSf) - LOGGf)
                + q3.w * (__logf(q3.w + EPSf) - LOGGf);
        }
        for (; e < R3c; e += STRIDEc) {
            float4 q = __ldcs(&qy[e]);
            k0 += q.x * (__logf(q.x + EPSf) - LOGGf)
                + q.y * (__logf(q.y + EPSf) - LOGGf)
                + q.z * (__logf(q.z + EPSf) - LOGGf)
                + q.w * (__logf(q.w + EPSf) - LOGGf);
        }
        kld = (k0 + k1) + (k2 + k3);
    }

    // ===== Region 4: best (3776 vec4s) =====================================
    if (gtid < R4c) {
        int e  = gtid;
        int rb = e / PC4c;
        int j4 = e - rb * PC4c;
        float4 a = __ldcs(&best[e]);
        float4 g = __ldcs(&best_gt[e]);
        int p0 = j4 * 2, p1 = p0 + 1;
        float dx = a.x - g.x, dy = a.y - g.y, dz = a.z - g.z, dw = a.w - g.w;
        float s01 = dx * dx + dy * dy;
        float s23 = dz * dz + dw * dw;
        bsum += s01 + s23;
        if (is_mark(p0)) blm += s01;
        if (is_mark(p1)) blm += s23;
    }

    // ---- block reduction: warp shfl, then thread 0 combines 32 warps ----
    #pragma unroll
    for (int o = 16; o > 0; o >>= 1) {
        recon += __shfl_down_sync(0xffffffffu, recon, o);
        disk  += __shfl_down_sync(0xffffffffu, disk,  o);
        lm    += __shfl_down_sync(0xffffffffu, lm,    o);
        kld   += __shfl_down_sync(0xffffffffu, kld,   o);
        bsum  += __shfl_down_sync(0xffffffffu, bsum,  o);
        blm   += __shfl_down_sync(0xffffffffu, blm,   o);
    }
    __shared__ float sw[NTHR / 32][6];
    int lane = t & 31, w = t >> 5;
    if (lane == 0) {
        sw[w][0] = recon; sw[w][1] = disk; sw[w][2] = lm;
        sw[w][3] = kld;   sw[w][4] = bsum; sw[w][5] = blm;
    }
    __syncthreads();

    __shared__ unsigned int s_ticket;
    if (t == 0) {
        float v[6] = {0, 0, 0, 0, 0, 0};
        #pragma unroll
        for (int i = 0; i < NTHR / 32; i++)
            #pragma unroll
            for (int k = 0; k < 6; k++) v[k] += sw[i][k];
        #pragma unroll
        for (int k = 0; k < 6; k++) atomicAdd(&g_acc[k], v[k]);
        __threadfence();
        s_ticket = atomicAdd(&g_cnt, 1u);
    }
    __syncthreads();

    // ---- last block: finalize, write out, reset for next graph replay ----
    if (s_ticket == NBLK - 1 && t == 0) {
        float a0 = atomicAdd(&g_acc[0], 0.f);
        float a1 = atomicAdd(&g_acc[1], 0.f);
        float a2 = atomicAdd(&g_acc[2], 0.f);
        float a3 = atomicAdd(&g_acc[3], 0.f);
        float a4 = atomicAdd(&g_acc[4], 0.f);
        float a5 = atomicAdd(&g_acc[5], 0.f);

        float recon_m = a0 / (float)(Bc * Sc * Dc);          // 16,777,216
        float disk_m  = a1 / (float)(Bc * Sc * Pc * Cc);     //  1,933,312
        float lmk_m   = a2 / (float)(Bc * Sc * 4 * Cc);      //     65,536
        float kld_m   = a3 / (float)(Bc * Sc);               //      8,192
        float bs_m    = a4 / (float)(Bc * Pc * Cc);          //     15,104
        float blm_m   = a5 / (float)(Bc * 4 * Cc);           //        512
        // total = BETA*kld + GAMMA*recon + (disk + ALPHA*lm) + (best + ALPHA*best_lm)
        out[0] = 0.1f * kld_m + recon_m + (disk_m + 10.f * lmk_m)
               + (bs_m + 10.f * blm_m);

        // reset accumulators for the next graph replay
        #pragma unroll
        for (int k = 0; k < 8; k++) g_acc[k] = 0.f;
        __threadfence();
        g_cnt = 0u;
    }
}

extern "C" void kernel_launch(void* const* d_in, const int* in_sizes, int n_in,
                              void* d_out, int out_size)
{
    const float4* zs      = (const float4*)d_in[0];
    const float4* rzs     = (const float4*)d_in[1];
    const float4* pts     = (const float4*)d_in[2];
    const float4* pts_gt  = (const float4*)d_in[3];
    const float4* qy      = (const float4*)d_in[4];
    // d_in[5] = logits : unused by the loss
    const float4* best    = (const float4*)d_in[6];
    const float4* best_gt = (const float4*)d_in[7];
    const int*    map32   = (const int*)d_in[8];
    // d_in[9] = vector_dims scalar : compile-time constant (512)

    loss_fused<<<NBLK, NTHR>>>(zs, rzs, pts, pts_gt, qy, best, best_gt,
                               map32, (float*)d_out);
}

// round 17
// speedup vs baseline: 1.1089x; 1.1089x over previous
#include <cuda_runtime.h>
#include <math.h>

// ---------------- problem constants (fixed shapes in the dataset) -----------
#define Bc   64
#define Sc   128
#define Dc   2048
#define Pc   118
#define Cc   2
#define Vc   512

#define D4c  (Dc/4)            // 512 float4 per zs/rzs row
#define PCc  (Pc*Cc)           // 236
#define PC4c (PCc/4)           // 59
#define V4c  (Vc/4)            // 128

#define NROW (Bc*Sc)           // 8192 rows
#define NRP  (NROW/2)          // 4096 row-pairs (2 rows = 1024 float4 = 1 block-iter)
#define R1c  (NROW*D4c)        // 4,194,304  recon vec4s
#define R2c  (NROW*PC4c)       //   483,328  pts vec4s
#define R3c  (NROW*V4c)        // 1,048,576  kld vec4s
#define R4c  (Bc*PC4c)         //     3,776  best vec4s

#define NBLK 304               // 2 CTAs/SM x 152 SMs — occ 2 (2048 thr/SM)
#define NTHR 1024
#define STRIDEc (NBLK*NTHR)    // 311,296

#define EPSf  1e-20f
#define LOGGf (-6.23832462503951f)   // log(1/512)

// global accumulators: recon, disk, lm, kld, best, bestlm  (+pad)
__device__ float        g_acc[8];
__device__ unsigned int g_cnt;

__device__ __forceinline__ bool is_mark(int p) {
    return (p == 0) | (p == 29) | (p == 88) | (p == 117);
}

__global__ __launch_bounds__(NTHR) void loss_fused(
    const float4* __restrict__ zs,
    const float4* __restrict__ rzs,
    const float4* __restrict__ pts,
    const float4* __restrict__ pts_gt,
    const float4* __restrict__ qy,
    const float4* __restrict__ best,
    const float4* __restrict__ best_gt,
    const int*    __restrict__ map32,   // mapping viewed as int32 words
    float*        __restrict__ out)
{
    const int t    = threadIdx.x;
    const int gtid = blockIdx.x * NTHR + t;

    // ---- detect mapping width once: int64 (JAX default) vs int32 ----------
    __shared__ int s_sh;
    if (t == 0) {
        int nz = 0;
        #pragma unroll
        for (int i = 0; i < 64; i++) nz |= map32[2 * i + 1];
        s_sh = (nz == 0) ? 1 : 0;   // shift: row<<1 for int64, row<<0 for int32
    }
    __syncthreads();
    const int sh = s_sh;

    float recon = 0.f, disk = 0.f, lm = 0.f, kld = 0.f, bsum = 0.f, blm = 0.f;

    // Cache policy: evict-first (__ldcs) on {zs, pts_gt, best, best_gt};
    // DEFAULT on gathered {rzs, pts} AND on qy. Resident target
    // rzs + pts + qy = 88.5MB < 126MB L2; warm-replay DRAM ~72MB.

    // ===== Region 1: recon — one row-PAIR (16KB) per block-iteration =======
    // 1024 threads: thread t owns float4 (t&511) of row (2*rp + (t>>9)).
    {
        float recon0 = 0.f, recon1 = 0.f;
        const int rsub = t >> 9;          // 0 or 1: which row of the pair
        const int col  = t & 511;
        int rp = blockIdx.x;
        for (; rp + NBLK < NRP; rp += 2 * NBLK) {
            int row0 = (rp << 1) + rsub;
            int row1 = ((rp + NBLK) << 1) + rsub;
            int m0 = __ldg(&map32[row0 << sh]);
            int m1 = __ldg(&map32[row1 << sh]);
            // gathered row g = (b<<7)+m ; b = row>>7 ; base = g<<9
            int rb0 = ((((row0 >> 7) << 7) + m0) << 9) + col;
            int rb1 = ((((row1 >> 7) << 7) + m1) << 9) + col;
            float4 z0 = __ldcs(&zs[(row0 << 9) + col]);
            float4 z1 = __ldcs(&zs[(row1 << 9) + col]);
            float4 r0 = rzs[rb0];
            float4 r1 = rzs[rb1];
            float dx0 = z0.x - r0.x, dy0 = z0.y - r0.y;
            float dz0 = z0.z - r0.z, dw0 = z0.w - r0.w;
            float dx1 = z1.x - r1.x, dy1 = z1.y - r1.y;
            float dz1 = z1.z - r1.z, dw1 = z1.w - r1.w;
            recon0 += dx0 * dx0 + dy0 * dy0 + dz0 * dz0 + dw0 * dw0;
            recon1 += dx1 * dx1 + dy1 * dy1 + dz1 * dz1 + dw1 * dw1;
        }
        for (; rp < NRP; rp += NBLK) {
            int row = (rp << 1) + rsub;
            int m   = __ldg(&map32[row << sh]);
            int rb  = ((((row >> 7) << 7) + m) << 9) + col;
            float4 z = __ldcs(&zs[(row << 9) + col]);
            float4 r = rzs[rb];
            float dx = z.x - r.x, dy = z.y - r.y, dz = z.z - r.z, dw = z.w - r.w;
            recon0 += dx * dx + dy * dy + dz * dz + dw * dw;
        }
        recon = recon0 + recon1;
    }

    // ===== Region 2: pts gather + landmark =================================
    {
        for (int e = gtid; e < R2c; e += STRIDEc) {
            int row = e / PC4c;
            int j4  = e - row * PC4c;
            int m   = __ldg(&map32[row << sh]);
            int pb  = (((row >> 7) << 7) + m) * PC4c + j4;
            float4 g = __ldcs(&pts_gt[e]);
            float4 x = pts[pb];
            int p0 = j4 * 2, p1 = p0 + 1;   // C=2: (x,y)->point p0, (z,w)->p1
            float dx = x.x - g.x, dy = x.y - g.y, dz = x.z - g.z, dw = x.w - g.w;
            float s01 = dx * dx + dy * dy;
            float s23 = dz * dz + dw * dw;
            disk += s01 + s23;
            if (is_mark(p0)) lm += s01;
            if (is_mark(p1)) lm += s23;
        }
    }

    // ===== Region 3: KL vs uniform — qy DEFAULT policy (L2-resident) =======
    {
        float k0 = 0.f, k1 = 0.f;
        int e = gtid;
        for (; e + STRIDEc < R3c; e += 2 * STRIDEc) {
            float4 q0 = qy[e];
            float4 q1 = qy[e + STRIDEc];
            k0 += q0.x * (__logf(q0.x + EPSf) - LOGGf)
                + q0.y * (__logf(q0.y + EPSf) - LOGGf)
                + q0.z * (__logf(q0.z + EPSf) - LOGGf)
                + q0.w * (__logf(q0.w + EPSf) - LOGGf);
            k1 += q1.x * (__logf(q1.x + EPSf) - LOGGf)
                + q1.y * (__logf(q1.y + EPSf) - LOGGf)
                + q1.z * (__logf(q1.z + EPSf) - LOGGf)
                + q1.w * (__logf(q1.w + EPSf) - LOGGf);
        }
        for (; e < R3c; e += STRIDEc) {
            float4 q = qy[e];
            k0 += q.x * (__logf(q.x + EPSf) - LOGGf)
                + q.y * (__logf(q.y + EPSf) - LOGGf)
                + q.z * (__logf(q.z + EPSf) - LOGGf)
                + q.w * (__logf(q.w + EPSf) - LOGGf);
        }
        kld = k0 + k1;
    }

    // ===== Region 4: best (3776 vec4s) =====================================
    if (gtid < R4c) {
        int e  = gtid;
        int rb = e / PC4c;
        int j4 = e - rb * PC4c;
        float4 a = __ldcs(&best[e]);
        float4 g = __ldcs(&best_gt[e]);
        int p0 = j4 * 2, p1 = p0 + 1;
        float dx = a.x - g.x, dy = a.y - g.y, dz = a.z - g.z, dw = a.w - g.w;
        float s01 = dx * dx + dy * dy;
        float s23 = dz * dz + dw * dw;
        bsum += s01 + s23;
        if (is_mark(p0)) blm += s01;
        if (is_mark(p1)) blm += s23;
    }

    // ---- block reduction: warp shfl, then thread 0 combines 32 warps ----
    #pragma unroll
    for (int o = 16; o > 0; o >>= 1) {
        recon += __shfl_down_sync(0xffffffffu, recon, o);
        disk  += __shfl_down_sync(0xffffffffu, disk,  o);
        lm    += __shfl_down_sync(0xffffffffu, lm,    o);
        kld   += __shfl_down_sync(0xffffffffu, kld,   o);
        bsum  += __shfl_down_sync(0xffffffffu, bsum,  o);
        blm   += __shfl_down_sync(0xffffffffu, blm,   o);
    }
    __shared__ float sw[NTHR / 32][6];
    int lane = t & 31, w = t >> 5;
    if (lane == 0) {
        sw[w][0] = recon; sw[w][1] = disk; sw[w][2] = lm;
        sw[w][3] = kld;   sw[w][4] = bsum; sw[w][5] = blm;
    }
    __syncthreads();

    __shared__ unsigned int s_ticket;
    if (t == 0) {
        float v[6] = {0, 0, 0, 0, 0, 0};
        #pragma unroll
        for (int i = 0; i < NTHR / 32; i++)
            #pragma unroll
            for (int k = 0; k < 6; k++) v[k] += sw[i][k];
        #pragma unroll
        for (int k = 0; k < 6; k++) atomicAdd(&g_acc[k], v[k]);
        __threadfence();
        s_ticket = atomicAdd(&g_cnt, 1u);
    }
    __syncthreads();

    // ---- last block: finalize, write out, reset for next graph replay ----
    if (s_ticket == NBLK - 1 && t == 0) {
        float a0 = atomicAdd(&g_acc[0], 0.f);
        float a1 = atomicAdd(&g_acc[1], 0.f);
        float a2 = atomicAdd(&g_acc[2], 0.f);
        float a3 = atomicAdd(&g_acc[3], 0.f);
        float a4 = atomicAdd(&g_acc[4], 0.f);
        float a5 = atomicAdd(&g_acc[5], 0.f);

        float recon_m = a0 / (float)(Bc * Sc * Dc);          // 16,777,216
        float disk_m  = a1 / (float)(Bc * Sc * Pc * Cc);     //  1,933,312
        float lmk_m   = a2 / (float)(Bc * Sc * 4 * Cc);      //     65,536
        float kld_m   = a3 / (float)(Bc * Sc);               //      8,192
        float bs_m    = a4 / (float)(Bc * Pc * Cc);          //     15,104
        float blm_m   = a5 / (float)(Bc * 4 * Cc);           //        512
        // total = BETA*kld + GAMMA*recon + (disk + ALPHA*lm) + (best + ALPHA*best_lm)
        out[0] = 0.1f * kld_m + recon_m + (disk_m + 10.f * lmk_m)
               + (bs_m + 10.f * blm_m);

        // reset accumulators for the next graph replay
        #pragma unroll
        for (int k = 0; k < 8; k++) g_acc[k] = 0.f;
        __threadfence();
        g_cnt = 0u;
    }
}

extern "C" void kernel_launch(void* const* d_in, const int* in_sizes, int n_in,
                              void* d_out, int out_size)
{
    const float4* zs      = (const float4*)d_in[0];
    const float4* rzs     = (const float4*)d_in[1];
    const float4* pts     = (const float4*)d_in[2];
    const float4* pts_gt  = (const float4*)d_in[3];
    const float4* qy      = (const float4*)d_in[4];
    // d_in[5] = logits : unused by the loss
    const float4* best    = (const float4*)d_in[6];
    const float4* best_gt = (const float4*)d_in[7];
    const int*    map32   = (const int*)d_in[8];
    // d_in[9] = vector_dims scalar : compile-time constant (512)

    loss_fused<<<NBLK, NTHR>>>(zs, rzs, pts, pts_gt, qy, best, best_gt,
                               map32, (float*)d_out);
}